// round 14
// baseline (speedup 1.0000x reference)
#include <cuda_runtime.h>
#include <cuda_bf16.h>
#include <cstdint>

#define B_    64
#define N_    128
#define LVLS  3
#define NT    32
#define TL    32
#define H_    256
#define OUT_  10

// SMEM layout (bytes)
#define HPAD  264
#define SM_H    0                                   // bf16 h[buf2][split2][64][264] = 135168
#define SM_C    135168                              // float c[64][257] = 65792
#define SM_VU   200960                              // float2 vu[1024]  = 8192
#define SM_SST  209152                              // float s_st[32][64] = 8192
#define SM_IDX  217344                              // int idx[32]
#define SM_SZ   217600

// W fragment-linear: [l][nt 128][ks 16][lane 32] uint4{bh0,bh1,bl0,bl1}
__device__ uint4  g_Wf[(size_t)LVLS * 128 * 16 * 32];   // 3 MB
__device__ float2 g_vu[LVLS * 1024];
__device__ float  g_partial[LVLS * NT * B_ * OUT_];

__device__ __forceinline__ void mma_bf16(float* d, uint32_t a0, uint32_t a1,
                                         uint32_t a2, uint32_t a3,
                                         uint32_t b0, uint32_t b1) {
    asm volatile(
        "mma.sync.aligned.m16n8k16.row.col.f32.bf16.bf16.f32 "
        "{%0,%1,%2,%3}, {%4,%5,%6,%7}, {%8,%9}, {%0,%1,%2,%3};"
        : "+f"(d[0]), "+f"(d[1]), "+f"(d[2]), "+f"(d[3])
        : "r"(a0), "r"(a1), "r"(a2), "r"(a3), "r"(b0), "r"(b1));
}
__device__ __forceinline__ float fsig(float x)  { return __fdividef(1.0f, 1.0f + __expf(-x)); }
__device__ __forceinline__ float ftanh(float x) {
    float s = __fdividef(1.0f, 1.0f + __expf(-2.0f * x));
    return fmaf(2.0f, s, -1.0f);
}
__device__ __forceinline__ uint32_t pk_bf2(float a, float b) {
    __nv_bfloat16 ba = __float2bfloat16(a), bb = __float2bfloat16(b);
    return (uint32_t)__bfloat16_as_ushort(ba) | ((uint32_t)__bfloat16_as_ushort(bb) << 16);
}

// ---------------------------------------------------------------------------
// prep: vu[gc] = (W_ih@w_enc, W_ih@b_enc + b_ih + b_hh), gc = 4u+g; and W_hh
// (bf16 hi/lo) baked into per-lane mma.sync B-fragment layout for direct LDG.
// One thread per (l,row) = 3072.
// ---------------------------------------------------------------------------
__global__ void prep_kernel(const float* __restrict__ W_ih,
                            const float* __restrict__ W_enc,
                            const float* __restrict__ b_enc,
                            const float* __restrict__ b_ih,
                            const float* __restrict__ b_hh,
                            const float* __restrict__ W_hh) {
    __shared__ float we[H_], be[H_];
    int tid = threadIdx.x;
    we[tid] = W_enc[tid]; be[tid] = b_enc[tid];
    __syncthreads();

    int r = blockIdx.x * 256 + tid;          // 0..3071
    int l = r >> 10, row = r & 1023;
    int g = row >> 8, u = row & 255;
    int gc = 4 * u + g;                      // gate column (interleaved)
    int nt = gc >> 3, lgrp = gc & 7;
    const float* Wi = W_ih + (size_t)r * H_;
    const float* Wh = W_hh + (size_t)r * H_;

    float sv = 0.f, su = 0.f;
    for (int ks = 0; ks < 16; ks++) {
#pragma unroll
        for (int tg = 0; tg < 4; tg++) {
            int k0 = ks * 16 + tg * 2;
            float wa = Wi[k0], wb = Wi[k0 + 1], wc = Wi[k0 + 8], wd = Wi[k0 + 9];
            sv = fmaf(wa, we[k0], fmaf(wb, we[k0 + 1], fmaf(wc, we[k0 + 8], fmaf(wd, we[k0 + 9], sv))));
            su = fmaf(wa, be[k0], fmaf(wb, be[k0 + 1], fmaf(wc, be[k0 + 8], fmaf(wd, be[k0 + 9], su))));
            float v00 = Wh[k0], v01 = Wh[k0 + 1], v10 = Wh[k0 + 8], v11 = Wh[k0 + 9];
            float h00 = __bfloat162float(__float2bfloat16(v00));
            float h01 = __bfloat162float(__float2bfloat16(v01));
            float h10 = __bfloat162float(__float2bfloat16(v10));
            float h11 = __bfloat162float(__float2bfloat16(v11));
            uint4 frag;
            frag.x = pk_bf2(v00, v01);                 // bh0 (k0,k0+1)
            frag.y = pk_bf2(v10, v11);                 // bh1 (k0+8,k0+9)
            frag.z = pk_bf2(v00 - h00, v01 - h01);     // bl0
            frag.w = pk_bf2(v10 - h10, v11 - h11);     // bl1
            g_Wf[(((size_t)l * 128 + nt) * 16 + ks) * 32 + lgrp * 4 + tg] = frag;
        }
    }
    g_vu[l * 1024 + gc] = make_float2(sv, su + b_ih[r] + b_hh[r]);
}

// ---------------------------------------------------------------------------
// LSTM via mma.sync: CTA per (l,t), 128 threads (4 warps). Warp w owns
// m-half (w>>1: rows 32mh..+32) x n-half (w&1: n-tiles 64nh..+64).
// 3-pass bf16-split MMA; h double-buffered; 1 barrier/step.
// ---------------------------------------------------------------------------
__global__ void __launch_bounds__(128, 1)
lstm_kernel(const float* __restrict__ bf,
            const int*   __restrict__ trunk_idx,
            const int*   __restrict__ trunk_len,
            const float* __restrict__ W_lin) {
    extern __shared__ char smem[];
    __nv_bfloat16* hb = reinterpret_cast<__nv_bfloat16*>(smem + SM_H);
    float*  csm = reinterpret_cast<float*>(smem + SM_C);
    float2* vu  = reinterpret_cast<float2*>(smem + SM_VU);
    float*  sst = reinterpret_cast<float*>(smem + SM_SST);
    int*    idx = reinterpret_cast<int*>(smem + SM_IDX);

    const int tid = threadIdx.x, lane = tid & 31, warp = tid >> 5;
    const int g = lane >> 2, tg = lane & 3;
    const int mh = warp >> 1, nh = warp & 1;
    const int l = blockIdx.x >> 5, t = blockIdx.x & 31;

    if (tid < TL) idx[tid] = trunk_idx[(l * NT + t) * TL + tid];
    __syncthreads();
    for (int i = tid; i < 1024; i += 128) vu[i] = g_vu[l * 1024 + i];
    for (int i = tid; i < 32 * 64; i += 128)
        sst[i] = bf[(i & 63) * N_ + idx[i >> 6]];
    for (int i = tid; i < 2 * 2 * 64 * HPAD / 2; i += 128)   // zero h (u32 fill)
        reinterpret_cast<uint32_t*>(hb)[i] = 0;
    for (int i = tid; i < 64 * 257; i += 128) csm[i] = 0.f;
    const int len = min(max(trunk_len[l * NT + t], 1), TL);
    __syncthreads();

    const uint4* gW = g_Wf + (size_t)l * 128 * 16 * 32;

    for (int step = 0; step < len; step++) {
        const int rbuf = step & 1, wbuf = rbuf ^ 1;
        const __nv_bfloat16* Hh = hb + (size_t)(rbuf * 2 + 0) * 64 * HPAD;
        const __nv_bfloat16* Hl = hb + (size_t)(rbuf * 2 + 1) * 64 * HPAD;
        __nv_bfloat16* Wh_ = hb + (size_t)(wbuf * 2 + 0) * 64 * HPAD;
        __nv_bfloat16* Wl_ = hb + (size_t)(wbuf * 2 + 1) * 64 * HPAD;

        for (int ch = 0; ch < 8; ch++) {
            float D[8][2][4];
#pragma unroll
            for (int q = 0; q < 8; q++)
#pragma unroll
                for (int m = 0; m < 2; m++)
#pragma unroll
                    for (int e = 0; e < 4; e++) D[q][m][e] = 0.f;

#pragma unroll 4
            for (int ks = 0; ks < 16; ks++) {
                uint32_t ah[2][4], al[2][4];
                const int c0 = ks * 16 + tg * 2;
#pragma unroll
                for (int m = 0; m < 2; m++) {
                    const int r0 = mh * 32 + m * 16 + g;
                    ah[m][0] = *reinterpret_cast<const uint32_t*>(Hh + r0 * HPAD + c0);
                    ah[m][1] = *reinterpret_cast<const uint32_t*>(Hh + (r0 + 8) * HPAD + c0);
                    ah[m][2] = *reinterpret_cast<const uint32_t*>(Hh + r0 * HPAD + c0 + 8);
                    ah[m][3] = *reinterpret_cast<const uint32_t*>(Hh + (r0 + 8) * HPAD + c0 + 8);
                    al[m][0] = *reinterpret_cast<const uint32_t*>(Hl + r0 * HPAD + c0);
                    al[m][1] = *reinterpret_cast<const uint32_t*>(Hl + (r0 + 8) * HPAD + c0);
                    al[m][2] = *reinterpret_cast<const uint32_t*>(Hl + r0 * HPAD + c0 + 8);
                    al[m][3] = *reinterpret_cast<const uint32_t*>(Hl + (r0 + 8) * HPAD + c0 + 8);
                }
#pragma unroll
                for (int q = 0; q < 8; q++) {
                    const int nt = nh * 64 + ch * 8 + q;
                    const uint4 Bv = __ldg(gW + ((size_t)nt * 16 + ks) * 32 + lane);
#pragma unroll
                    for (int m = 0; m < 2; m++) {
                        mma_bf16(D[q][m], ah[m][0], ah[m][1], ah[m][2], ah[m][3], Bv.x, Bv.y);
                        mma_bf16(D[q][m], al[m][0], al[m][1], al[m][2], al[m][3], Bv.x, Bv.y);
                        mma_bf16(D[q][m], ah[m][0], ah[m][1], ah[m][2], ah[m][3], Bv.z, Bv.w);
                    }
                }
            }

            // Activations for this chunk (each lane: one (row,unit) per (q,m))
#pragma unroll
            for (int q = 0; q < 8; q++) {
                const int nt = nh * 64 + ch * 8 + q;
#pragma unroll
                for (int m = 0; m < 2; m++) {
                    float* d = D[q][m];
                    float x0 = __shfl_xor_sync(0xffffffffu, d[0], 1);
                    float x1 = __shfl_xor_sync(0xffffffffu, d[1], 1);
                    float x2 = __shfl_xor_sync(0xffffffffu, d[2], 1);
                    float x3 = __shfl_xor_sync(0xffffffffu, d[3], 1);
                    const int odd = tg & 1;
                    const int u = nt * 2 + (tg >> 1);
                    const int row = mh * 32 + m * 16 + g + 8 * odd;
                    float gi = odd ? x2 : d[0];
                    float gf = odd ? x3 : d[1];
                    float gg = odd ? d[2] : x0;
                    float go = odd ? d[3] : x1;
                    const float sm = sst[step * 64 + row];
                    float2 vi = vu[4 * u], vf = vu[4 * u + 1],
                           vg = vu[4 * u + 2], vo = vu[4 * u + 3];
                    gi += fmaf(sm, vi.x, vi.y);
                    gf += fmaf(sm, vf.x, vf.y);
                    gg += fmaf(sm, vg.x, vg.y);
                    go += fmaf(sm, vo.x, vo.y);
                    float cc = csm[row * 257 + u];
                    float cm = fmaf(fsig(gf), cc, fsig(gi) * ftanh(gg));
                    csm[row * 257 + u] = cm;
                    float hv = fsig(go) * ftanh(cm);
                    __nv_bfloat16 hbv = __float2bfloat16(hv);
                    Wh_[row * HPAD + u] = hbv;
                    Wl_[row * HPAD + u] = __float2bfloat16(hv - __bfloat162float(hbv));
                }
            }
        }
        __syncthreads();   // all h(wbuf) writes visible before next step's reads
    }

    // Epilogue: partial[b][o] = h_last[b] @ W_lin[l]
    const __nv_bfloat16* Fh = hb + (size_t)((len & 1) * 2 + 0) * 64 * HPAD;
    const __nv_bfloat16* Fl = hb + (size_t)((len & 1) * 2 + 1) * 64 * HPAD;
    if (tid < 64) {
        float acc[OUT_];
#pragma unroll
        for (int o = 0; o < OUT_; o++) acc[o] = 0.f;
        for (int u = 0; u < H_; u++) {
            float hv = __bfloat162float(Fh[tid * HPAD + u]) +
                       __bfloat162float(Fl[tid * HPAD + u]);
            const float* wl = W_lin + ((size_t)l * H_ + u) * OUT_;
#pragma unroll
            for (int o = 0; o < OUT_; o++) acc[o] = fmaf(hv, wl[o], acc[o]);
        }
#pragma unroll
        for (int o = 0; o < OUT_; o++)
            g_partial[((l * NT + t) * B_ + tid) * OUT_ + o] = acc[o];
    }
}

// ---------------------------------------------------------------------------
__global__ void reduce_kernel(const float* __restrict__ b_lin,
                              float* __restrict__ out) {
    int i = blockIdx.x * blockDim.x + threadIdx.x;
    if (i >= B_ * OUT_) return;
    int b = i / OUT_, o = i % OUT_;
    float s = 0.f;
#pragma unroll
    for (int l = 0; l < LVLS; l++) {
        s += b_lin[l * OUT_ + o];
        for (int t = 0; t < NT; t++)
            s += g_partial[((l * NT + t) * B_ + b) * OUT_ + o];
    }
    out[i] = s;
}

// ---------------------------------------------------------------------------
extern "C" void kernel_launch(void* const* d_in, const int* in_sizes, int n_in,
                              void* d_out, int out_size) {
    const float* batch_feature = (const float*)d_in[0];
    const int*   trunk_idx     = (const int*)  d_in[1];
    const int*   trunk_len     = (const int*)  d_in[2];
    const float* W_enc         = (const float*)d_in[3];
    const float* b_enc         = (const float*)d_in[4];
    const float* W_ih          = (const float*)d_in[5];
    const float* W_hh          = (const float*)d_in[6];
    const float* b_ih          = (const float*)d_in[7];
    const float* b_hh          = (const float*)d_in[8];
    const float* W_lin         = (const float*)d_in[9];
    const float* b_lin         = (const float*)d_in[10];
    float* out = (float*)d_out;

    cudaFuncSetAttribute(lstm_kernel,
                         cudaFuncAttributeMaxDynamicSharedMemorySize, SM_SZ);

    prep_kernel<<<12, 256>>>(W_ih, W_enc, b_enc, b_ih, b_hh, W_hh);
    lstm_kernel<<<LVLS * NT, 128, SM_SZ>>>(batch_feature, trunk_idx, trunk_len, W_lin);
    reduce_kernel<<<(B_ * OUT_ + 127) / 128, 128>>>(b_lin, out);
}

// round 15
// speedup vs baseline: 2.5296x; 2.5296x over previous
#include <cuda_runtime.h>
#include <cuda_bf16.h>
#include <cstdint>

#define B_    64
#define N_    128
#define LVLS  3
#define NT    32
#define TL    32
#define H_    256
#define OUT_  10
#define BC    4
#define MB    16
#define NJOBS (LVLS*NT*BC)   // 384

// SMEM layout (bytes). h: bf16 [buf2][split2][16][HPAD]
#define HPAD  264
#define SM_H    0                         // 2*2*16*264*2 = 33792
#define SM_C    33792                     // float c[16][257] = 16448
#define SM_VU   50240                     // float2 vu[1024] = 8192
#define SM_SST  58432                     // float sst[32][16] = 2048
#define SM_IDX  60480                     // int idx[32] = 128
#define SM_MISC 60608                     // int misc[2]
#define SM_SZ   60672

// W fragment-linear: [l][nt 128][ks 16][lane 32] uint4{bh0,bh1,bl0,bl1}
__device__ uint4  g_Wf[(size_t)LVLS * 128 * 16 * 32];   // 3 MB
__device__ float2 g_vu[LVLS * 1024];
__device__ float  g_partial[NJOBS * MB * OUT_];
__device__ int    g_order[NJOBS];
__device__ int    g_ticket;

__device__ __forceinline__ void mma_bf16(float* d, uint32_t a0, uint32_t a1,
                                         uint32_t a2, uint32_t a3,
                                         uint32_t b0, uint32_t b1) {
    asm volatile(
        "mma.sync.aligned.m16n8k16.row.col.f32.bf16.bf16.f32 "
        "{%0,%1,%2,%3}, {%4,%5,%6,%7}, {%8,%9}, {%0,%1,%2,%3};"
        : "+f"(d[0]), "+f"(d[1]), "+f"(d[2]), "+f"(d[3])
        : "r"(a0), "r"(a1), "r"(a2), "r"(a3), "r"(b0), "r"(b1));
}
__device__ __forceinline__ float fsig(float x)  { return __fdividef(1.0f, 1.0f + __expf(-x)); }
__device__ __forceinline__ float ftanh(float x) {
    float s = __fdividef(1.0f, 1.0f + __expf(-2.0f * x));
    return fmaf(2.0f, s, -1.0f);
}
__device__ __forceinline__ uint32_t pk_bf2(float a, float b) {
    __nv_bfloat16 ba = __float2bfloat16(a), bb = __float2bfloat16(b);
    return (uint32_t)__bfloat16_as_ushort(ba) | ((uint32_t)__bfloat16_as_ushort(bb) << 16);
}

// ---------------------------------------------------------------------------
// prep: one WARP per (l,row). Lane handles slots (ks,tg); sv/su shfl-reduced.
// Produces vu[gc] and mma B-fragment-linear W images (same math as R13).
// ---------------------------------------------------------------------------
__global__ void prep_kernel(const float* __restrict__ W_ih,
                            const float* __restrict__ W_enc,
                            const float* __restrict__ b_enc,
                            const float* __restrict__ b_ih,
                            const float* __restrict__ b_hh,
                            const float* __restrict__ W_hh) {
    __shared__ float we[H_], be[H_];
    int tid = threadIdx.x;
    we[tid] = W_enc[tid]; be[tid] = b_enc[tid];
    __syncthreads();

    int wg  = blockIdx.x * 8 + (tid >> 5);   // 0..3071 = (l,row)
    int lane = tid & 31;
    int l = wg >> 10, row = wg & 1023;
    int g = row >> 8, u = row & 255;
    int gc = 4 * u + g;
    int nt = gc >> 3, lgrp = gc & 7;
    const float* Wi = W_ih + (size_t)wg * H_;
    const float* Wh = W_hh + (size_t)wg * H_;

    float sv = 0.f, su = 0.f;
#pragma unroll
    for (int rep = 0; rep < 2; rep++) {
        int slot = lane + 32 * rep;          // 0..63
        int ks = slot >> 2, tg = slot & 3;
        int k0 = ks * 16 + tg * 2;
        float wa = Wi[k0], wb = Wi[k0 + 1], wc = Wi[k0 + 8], wd = Wi[k0 + 9];
        sv += wa * we[k0] + wb * we[k0 + 1] + wc * we[k0 + 8] + wd * we[k0 + 9];
        su += wa * be[k0] + wb * be[k0 + 1] + wc * be[k0 + 8] + wd * be[k0 + 9];
        float v00 = Wh[k0], v01 = Wh[k0 + 1], v10 = Wh[k0 + 8], v11 = Wh[k0 + 9];
        float h00 = __bfloat162float(__float2bfloat16(v00));
        float h01 = __bfloat162float(__float2bfloat16(v01));
        float h10 = __bfloat162float(__float2bfloat16(v10));
        float h11 = __bfloat162float(__float2bfloat16(v11));
        uint4 frag;
        frag.x = pk_bf2(v00, v01);
        frag.y = pk_bf2(v10, v11);
        frag.z = pk_bf2(v00 - h00, v01 - h01);
        frag.w = pk_bf2(v10 - h10, v11 - h11);
        g_Wf[(((size_t)l * 128 + nt) * 16 + ks) * 32 + lgrp * 4 + tg] = frag;
    }
#pragma unroll
    for (int o = 16; o; o >>= 1) {
        sv += __shfl_xor_sync(0xffffffffu, sv, o);
        su += __shfl_xor_sync(0xffffffffu, su, o);
    }
    if (lane == 0)
        g_vu[l * 1024 + gc] = make_float2(sv, su + b_ih[wg] + b_hh[wg]);
}

// ---------------------------------------------------------------------------
// order: LPT rank + ticket reset (proven from R10).
// ---------------------------------------------------------------------------
__global__ void order_kernel(const int* __restrict__ trunk_len) {
    __shared__ int len_s[NJOBS];
    int i = threadIdx.x;
    int l = i >> 7, t = (i >> 2) & 31;
    int L = trunk_len[l * NT + t];
    L = min(max(L, 1), TL);
    len_s[i] = L;
    __syncthreads();
    int Li = len_s[i];
    int rank = 0;
    for (int k = 0; k < NJOBS; k++) {
        int Lk = len_s[k];
        rank += (Lk > Li) || (Lk == Li && k < i);
    }
    g_order[rank] = i;
    if (i == 0) g_ticket = 0;
}

// ---------------------------------------------------------------------------
// LSTM via mma.sync, M=16 jobs: persistent CTAs (occ 2), LPT ticket over 384
// (l,t,bc) jobs. 128 threads/CTA; warp w owns gate cols [w*256,(w+1)*256).
// 3-pass bf16-split MMA (proven R13); h double-buffered; 1 barrier/step.
// ---------------------------------------------------------------------------
__global__ void __launch_bounds__(128, 2)
lstm_kernel(const float* __restrict__ bf,
            const int*   __restrict__ trunk_idx,
            const int*   __restrict__ trunk_len,
            const float* __restrict__ W_lin) {
    extern __shared__ char smem[];
    __nv_bfloat16* hb = reinterpret_cast<__nv_bfloat16*>(smem + SM_H);
    float*  csm = reinterpret_cast<float*>(smem + SM_C);
    float2* vu  = reinterpret_cast<float2*>(smem + SM_VU);
    float*  sst = reinterpret_cast<float*>(smem + SM_SST);
    int*    idx = reinterpret_cast<int*>(smem + SM_IDX);
    int*    misc = reinterpret_cast<int*>(smem + SM_MISC);

    const int tid = threadIdx.x, lane = tid & 31, warp = tid >> 5;
    const int g = lane >> 2, tg = lane & 3;

    for (;;) {
        if (tid == 0) {
            int tk = atomicAdd(&g_ticket, 1);
            misc[0] = (tk < NJOBS) ? g_order[tk] : -1;
        }
        __syncthreads();
        const int job = misc[0];
        if (job < 0) break;
        const int l = job >> 7, t = (job >> 2) & 31, bc = job & 3;

        if (tid < TL) idx[tid] = trunk_idx[(l * NT + t) * TL + tid];
        if (tid == 0) misc[1] = min(max(trunk_len[l * NT + t], 1), TL);
        __syncthreads();
        for (int i = tid; i < 1024; i += 128) vu[i] = g_vu[l * 1024 + i];
        for (int i = tid; i < 32 * 16; i += 128)
            sst[i] = bf[(bc * MB + (i & 15)) * N_ + idx[i >> 4]];
        for (int i = tid; i < 8448; i += 128)
            reinterpret_cast<uint32_t*>(hb)[i] = 0;      // zero both h bufs
        for (int i = tid; i < 16 * 257; i += 128) csm[i] = 0.f;
        __syncthreads();
        const int len = misc[1];

        const uint4* gW = g_Wf + (size_t)l * 128 * 16 * 32;

        for (int step = 0; step < len; step++) {
            const int rbuf = step & 1, wbuf = rbuf ^ 1;
            const __nv_bfloat16* Hh = hb + (size_t)(rbuf * 2 + 0) * 16 * HPAD;
            const __nv_bfloat16* Hl = hb + (size_t)(rbuf * 2 + 1) * 16 * HPAD;
            __nv_bfloat16* Wh_ = hb + (size_t)(wbuf * 2 + 0) * 16 * HPAD;
            __nv_bfloat16* Wl_ = hb + (size_t)(wbuf * 2 + 1) * 16 * HPAD;

            for (int ch = 0; ch < 4; ch++) {
                float D[8][4];
#pragma unroll
                for (int q = 0; q < 8; q++)
#pragma unroll
                    for (int e = 0; e < 4; e++) D[q][e] = 0.f;

#pragma unroll 4
                for (int ks = 0; ks < 16; ks++) {
                    const int c0 = ks * 16 + tg * 2;
                    uint32_t ah0 = *reinterpret_cast<const uint32_t*>(Hh + g * HPAD + c0);
                    uint32_t ah1 = *reinterpret_cast<const uint32_t*>(Hh + (g + 8) * HPAD + c0);
                    uint32_t ah2 = *reinterpret_cast<const uint32_t*>(Hh + g * HPAD + c0 + 8);
                    uint32_t ah3 = *reinterpret_cast<const uint32_t*>(Hh + (g + 8) * HPAD + c0 + 8);
                    uint32_t al0 = *reinterpret_cast<const uint32_t*>(Hl + g * HPAD + c0);
                    uint32_t al1 = *reinterpret_cast<const uint32_t*>(Hl + (g + 8) * HPAD + c0);
                    uint32_t al2 = *reinterpret_cast<const uint32_t*>(Hl + g * HPAD + c0 + 8);
                    uint32_t al3 = *reinterpret_cast<const uint32_t*>(Hl + (g + 8) * HPAD + c0 + 8);
#pragma unroll
                    for (int q = 0; q < 8; q++) {
                        const int nt = warp * 32 + ch * 8 + q;
                        const uint4 Bv = __ldg(gW + ((size_t)nt * 16 + ks) * 32 + lane);
                        mma_bf16(D[q], ah0, ah1, ah2, ah3, Bv.x, Bv.y);
                        mma_bf16(D[q], al0, al1, al2, al3, Bv.x, Bv.y);
                        mma_bf16(D[q], ah0, ah1, ah2, ah3, Bv.z, Bv.w);
                    }
                }

                // Activations (mapping identical to R13, m16 tile)
#pragma unroll
                for (int q = 0; q < 8; q++) {
                    float* d = D[q];
                    float x0 = __shfl_xor_sync(0xffffffffu, d[0], 1);
                    float x1 = __shfl_xor_sync(0xffffffffu, d[1], 1);
                    float x2 = __shfl_xor_sync(0xffffffffu, d[2], 1);
                    float x3 = __shfl_xor_sync(0xffffffffu, d[3], 1);
                    const int odd = tg & 1;
                    const int u = warp * 64 + (ch * 8 + q) * 2 + (tg >> 1);
                    const int row = g + 8 * odd;
                    float gi = odd ? x2 : d[0];
                    float gf = odd ? x3 : d[1];
                    float gg = odd ? d[2] : x0;
                    float go = odd ? d[3] : x1;
                    const float sm = sst[step * 16 + row];
                    float2 vi = vu[4 * u], vf = vu[4 * u + 1],
                           vg = vu[4 * u + 2], vo = vu[4 * u + 3];
                    gi += fmaf(sm, vi.x, vi.y);
                    gf += fmaf(sm, vf.x, vf.y);
                    gg += fmaf(sm, vg.x, vg.y);
                    go += fmaf(sm, vo.x, vo.y);
                    float cc = csm[row * 257 + u];
                    float cm = fmaf(fsig(gf), cc, fsig(gi) * ftanh(gg));
                    csm[row * 257 + u] = cm;
                    float hv = fsig(go) * ftanh(cm);
                    __nv_bfloat16 hbv = __float2bfloat16(hv);
                    Wh_[row * HPAD + u] = hbv;
                    Wl_[row * HPAD + u] = __float2bfloat16(hv - __bfloat162float(hbv));
                }
            }
            __syncthreads();   // h(wbuf) complete before next step reads it
        }

        // Epilogue: partial[m][o] = h_last[m] @ W_lin[l]
        {
            const __nv_bfloat16* Fh = hb + (size_t)((len & 1) * 2 + 0) * 16 * HPAD;
            const __nv_bfloat16* Fl = hb + (size_t)((len & 1) * 2 + 1) * 16 * HPAD;
            for (int i = tid; i < MB * OUT_; i += 128) {
                int m = i / OUT_, o = i - m * OUT_;
                const float* wl = W_lin + (size_t)l * H_ * OUT_ + o;
                float s = 0.f;
#pragma unroll 8
                for (int u = 0; u < H_; u++) {
                    float hv = __bfloat162float(Fh[m * HPAD + u]) +
                               __bfloat162float(Fl[m * HPAD + u]);
                    s = fmaf(hv, __ldg(wl + u * OUT_), s);
                }
                g_partial[(job * MB + m) * OUT_ + o] = s;
            }
        }
        __syncthreads();   // protect smem before next job
    }
}

// ---------------------------------------------------------------------------
__global__ void reduce_kernel(const float* __restrict__ b_lin,
                              float* __restrict__ out) {
    int i = blockIdx.x * blockDim.x + threadIdx.x;
    if (i >= B_ * OUT_) return;
    int b = i / OUT_, o = i % OUT_;
    int bc = b / MB, m = b % MB;
    float s = 0.f;
#pragma unroll
    for (int l = 0; l < LVLS; l++) {
        s += b_lin[l * OUT_ + o];
        for (int t = 0; t < NT; t++) {
            int job = (l * NT + t) * BC + bc;
            s += g_partial[(job * MB + m) * OUT_ + o];
        }
    }
    out[i] = s;
}

// ---------------------------------------------------------------------------
extern "C" void kernel_launch(void* const* d_in, const int* in_sizes, int n_in,
                              void* d_out, int out_size) {
    const float* batch_feature = (const float*)d_in[0];
    const int*   trunk_idx     = (const int*)  d_in[1];
    const int*   trunk_len     = (const int*)  d_in[2];
    const float* W_enc         = (const float*)d_in[3];
    const float* b_enc         = (const float*)d_in[4];
    const float* W_ih          = (const float*)d_in[5];
    const float* W_hh          = (const float*)d_in[6];
    const float* b_ih          = (const float*)d_in[7];
    const float* b_hh          = (const float*)d_in[8];
    const float* W_lin         = (const float*)d_in[9];
    const float* b_lin         = (const float*)d_in[10];
    float* out = (float*)d_out;

    cudaFuncSetAttribute(lstm_kernel,
                         cudaFuncAttributeMaxDynamicSharedMemorySize, SM_SZ);

    prep_kernel<<<384, 256>>>(W_ih, W_enc, b_enc, b_ih, b_hh, W_hh);
    order_kernel<<<1, NJOBS>>>(trunk_len);
    lstm_kernel<<<296, 128, SM_SZ>>>(batch_feature, trunk_idx, trunk_len, W_lin);
    reduce_kernel<<<(B_ * OUT_ + 127) / 128, 128>>>(b_lin, out);
}

// round 16
// speedup vs baseline: 3.4689x; 1.3713x over previous
#include <cuda_runtime.h>
#include <cuda_bf16.h>
#include <cstdint>

#define B_    64
#define N_    128
#define LVLS  3
#define NT    32
#define TL    32
#define H_    256
#define OUT_  10
#define BC    4
#define MB    16
#define NJOBS (LVLS*NT*BC)   // 384

// SMEM layout (bytes). h: bf16 [buf2][split2][16][HPAD]
#define HPAD  264
#define SM_H    0                         // 2*2*16*264*2 = 33792
#define SM_C    33792                     // float c[16][257] = 16448
#define SM_VU   50240                     // float2 vu[1024] = 8192
#define SM_SST  58432                     // float sst[32][16] = 2048
#define SM_IDX  60480                     // int idx[32] = 128
#define SM_MISC 60608                     // int misc[2]
#define SM_SZ   60672

// W fragment-linear (bf16 hi only): [l][nt 128][ks 16][lane 32] uint2{bh0,bh1}
__device__ uint2  g_Wf[(size_t)LVLS * 128 * 16 * 32];   // 1.5 MB
__device__ float2 g_vu[LVLS * 1024];
__device__ float  g_partial[NJOBS * MB * OUT_];
__device__ int    g_order[NJOBS];
__device__ int    g_ticket;

__device__ __forceinline__ void mma_bf16(float* d, uint32_t a0, uint32_t a1,
                                         uint32_t a2, uint32_t a3,
                                         uint32_t b0, uint32_t b1) {
    asm volatile(
        "mma.sync.aligned.m16n8k16.row.col.f32.bf16.bf16.f32 "
        "{%0,%1,%2,%3}, {%4,%5,%6,%7}, {%8,%9}, {%0,%1,%2,%3};"
        : "+f"(d[0]), "+f"(d[1]), "+f"(d[2]), "+f"(d[3])
        : "r"(a0), "r"(a1), "r"(a2), "r"(a3), "r"(b0), "r"(b1));
}
__device__ __forceinline__ float fsig(float x)  { return __fdividef(1.0f, 1.0f + __expf(-x)); }
__device__ __forceinline__ float ftanh(float x) {
    float s = __fdividef(1.0f, 1.0f + __expf(-2.0f * x));
    return fmaf(2.0f, s, -1.0f);
}
__device__ __forceinline__ uint32_t pk_bf2(float a, float b) {
    __nv_bfloat16 ba = __float2bfloat16(a), bb = __float2bfloat16(b);
    return (uint32_t)__bfloat16_as_ushort(ba) | ((uint32_t)__bfloat16_as_ushort(bb) << 16);
}

// ---------------------------------------------------------------------------
// prep: one WARP per (l,row). Lane handles slots (ks,tg); sv/su shfl-reduced.
// Produces vu[gc] and bf16-hi mma B-fragment-linear W images.
// ---------------------------------------------------------------------------
__global__ void prep_kernel(const float* __restrict__ W_ih,
                            const float* __restrict__ W_enc,
                            const float* __restrict__ b_enc,
                            const float* __restrict__ b_ih,
                            const float* __restrict__ b_hh,
                            const float* __restrict__ W_hh) {
    __shared__ float we[H_], be[H_];
    int tid = threadIdx.x;
    we[tid] = W_enc[tid]; be[tid] = b_enc[tid];
    __syncthreads();

    int wg  = blockIdx.x * 8 + (tid >> 5);   // 0..3071 = (l,row)
    int lane = tid & 31;
    int l = wg >> 10, row = wg & 1023;
    int g = row >> 8, u = row & 255;
    int gc = 4 * u + g;
    int nt = gc >> 3, lgrp = gc & 7;
    const float* Wi = W_ih + (size_t)wg * H_;
    const float* Wh = W_hh + (size_t)wg * H_;

    float sv = 0.f, su = 0.f;
#pragma unroll
    for (int rep = 0; rep < 2; rep++) {
        int slot = lane + 32 * rep;          // 0..63
        int ks = slot >> 2, tg = slot & 3;
        int k0 = ks * 16 + tg * 2;
        float wa = Wi[k0], wb = Wi[k0 + 1], wc = Wi[k0 + 8], wd = Wi[k0 + 9];
        sv += wa * we[k0] + wb * we[k0 + 1] + wc * we[k0 + 8] + wd * we[k0 + 9];
        su += wa * be[k0] + wb * be[k0 + 1] + wc * be[k0 + 8] + wd * be[k0 + 9];
        uint2 frag;
        frag.x = pk_bf2(Wh[k0], Wh[k0 + 1]);       // bh0 (k0,k0+1)
        frag.y = pk_bf2(Wh[k0 + 8], Wh[k0 + 9]);   // bh1 (k0+8,k0+9)
        g_Wf[(((size_t)l * 128 + nt) * 16 + ks) * 32 + lgrp * 4 + tg] = frag;
    }
#pragma unroll
    for (int o = 16; o; o >>= 1) {
        sv += __shfl_xor_sync(0xffffffffu, sv, o);
        su += __shfl_xor_sync(0xffffffffu, su, o);
    }
    if (lane == 0)
        g_vu[l * 1024 + gc] = make_float2(sv, su + b_ih[wg] + b_hh[wg]);
}

// ---------------------------------------------------------------------------
// order: LPT rank + ticket reset.
// ---------------------------------------------------------------------------
__global__ void order_kernel(const int* __restrict__ trunk_len) {
    __shared__ int len_s[NJOBS];
    int i = threadIdx.x;
    int l = i >> 7, t = (i >> 2) & 31;
    int L = trunk_len[l * NT + t];
    L = min(max(L, 1), TL);
    len_s[i] = L;
    __syncthreads();
    int Li = len_s[i];
    int rank = 0;
    for (int k = 0; k < NJOBS; k++) {
        int Lk = len_s[k];
        rank += (Lk > Li) || (Lk == Li && k < i);
    }
    g_order[rank] = i;
    if (i == 0) g_ticket = 0;
}

// ---------------------------------------------------------------------------
// LSTM via mma.sync, M=16 jobs, 2-pass h-split (Ah*Bh + Al*Bh; W bf16-hi).
// Persistent CTAs (occ 2), LPT ticket over 384 (l,t,bc) jobs. 128 thr/CTA;
// warp w owns gate cols [w*256,(w+1)*256). h double-buffered; 1 barrier/step.
// ---------------------------------------------------------------------------
__global__ void __launch_bounds__(128, 2)
lstm_kernel(const float* __restrict__ bf,
            const int*   __restrict__ trunk_idx,
            const int*   __restrict__ trunk_len,
            const float* __restrict__ W_lin) {
    extern __shared__ char smem[];
    __nv_bfloat16* hb = reinterpret_cast<__nv_bfloat16*>(smem + SM_H);
    float*  csm = reinterpret_cast<float*>(smem + SM_C);
    float2* vu  = reinterpret_cast<float2*>(smem + SM_VU);
    float*  sst = reinterpret_cast<float*>(smem + SM_SST);
    int*    idx = reinterpret_cast<int*>(smem + SM_IDX);
    int*    misc = reinterpret_cast<int*>(smem + SM_MISC);

    const int tid = threadIdx.x, lane = tid & 31, warp = tid >> 5;
    const int g = lane >> 2, tg = lane & 3;

    for (;;) {
        if (tid == 0) {
            int tk = atomicAdd(&g_ticket, 1);
            misc[0] = (tk < NJOBS) ? g_order[tk] : -1;
        }
        __syncthreads();
        const int job = misc[0];
        if (job < 0) break;
        const int l = job >> 7, t = (job >> 2) & 31, bc = job & 3;

        if (tid < TL) idx[tid] = trunk_idx[(l * NT + t) * TL + tid];
        if (tid == 0) misc[1] = min(max(trunk_len[l * NT + t], 1), TL);
        __syncthreads();
        for (int i = tid; i < 1024; i += 128) vu[i] = g_vu[l * 1024 + i];
        for (int i = tid; i < 32 * 16; i += 128)
            sst[i] = bf[(bc * MB + (i & 15)) * N_ + idx[i >> 4]];
        for (int i = tid; i < 8448; i += 128)
            reinterpret_cast<uint32_t*>(hb)[i] = 0;      // zero both h bufs
        for (int i = tid; i < 16 * 257; i += 128) csm[i] = 0.f;
        __syncthreads();
        const int len = misc[1];

        const uint2* gW = g_Wf + (size_t)l * 128 * 16 * 32;

        for (int step = 0; step < len; step++) {
            const int rbuf = step & 1, wbuf = rbuf ^ 1;
            const __nv_bfloat16* Hh = hb + (size_t)(rbuf * 2 + 0) * 16 * HPAD;
            const __nv_bfloat16* Hl = hb + (size_t)(rbuf * 2 + 1) * 16 * HPAD;
            __nv_bfloat16* Wh_ = hb + (size_t)(wbuf * 2 + 0) * 16 * HPAD;
            __nv_bfloat16* Wl_ = hb + (size_t)(wbuf * 2 + 1) * 16 * HPAD;

            for (int ch = 0; ch < 4; ch++) {
                float D[8][4];
#pragma unroll
                for (int q = 0; q < 8; q++)
#pragma unroll
                    for (int e = 0; e < 4; e++) D[q][e] = 0.f;

#pragma unroll 4
                for (int ks = 0; ks < 16; ks++) {
                    const int c0 = ks * 16 + tg * 2;
                    uint32_t ah0 = *reinterpret_cast<const uint32_t*>(Hh + g * HPAD + c0);
                    uint32_t ah1 = *reinterpret_cast<const uint32_t*>(Hh + (g + 8) * HPAD + c0);
                    uint32_t ah2 = *reinterpret_cast<const uint32_t*>(Hh + g * HPAD + c0 + 8);
                    uint32_t ah3 = *reinterpret_cast<const uint32_t*>(Hh + (g + 8) * HPAD + c0 + 8);
                    uint32_t al0 = *reinterpret_cast<const uint32_t*>(Hl + g * HPAD + c0);
                    uint32_t al1 = *reinterpret_cast<const uint32_t*>(Hl + (g + 8) * HPAD + c0);
                    uint32_t al2 = *reinterpret_cast<const uint32_t*>(Hl + g * HPAD + c0 + 8);
                    uint32_t al3 = *reinterpret_cast<const uint32_t*>(Hl + (g + 8) * HPAD + c0 + 8);
#pragma unroll
                    for (int q = 0; q < 8; q++) {
                        const int nt = warp * 32 + ch * 8 + q;
                        const uint2 Bv = __ldg(gW + ((size_t)nt * 16 + ks) * 32 + lane);
                        mma_bf16(D[q], ah0, ah1, ah2, ah3, Bv.x, Bv.y);
                        mma_bf16(D[q], al0, al1, al2, al3, Bv.x, Bv.y);
                    }
                }

                // Activations (mapping identical to R14)
#pragma unroll
                for (int q = 0; q < 8; q++) {
                    float* d = D[q];
                    float x0 = __shfl_xor_sync(0xffffffffu, d[0], 1);
                    float x1 = __shfl_xor_sync(0xffffffffu, d[1], 1);
                    float x2 = __shfl_xor_sync(0xffffffffu, d[2], 1);
                    float x3 = __shfl_xor_sync(0xffffffffu, d[3], 1);
                    const int odd = tg & 1;
                    const int u = warp * 64 + (ch * 8 + q) * 2 + (tg >> 1);
                    const int row = g + 8 * odd;
                    float gi = odd ? x2 : d[0];
                    float gf = odd ? x3 : d[1];
                    float gg = odd ? d[2] : x0;
                    float go = odd ? d[3] : x1;
                    const float sm = sst[step * 16 + row];
                    float2 vi = vu[4 * u], vf = vu[4 * u + 1],
                           vg = vu[4 * u + 2], vo = vu[4 * u + 3];
                    gi += fmaf(sm, vi.x, vi.y);
                    gf += fmaf(sm, vf.x, vf.y);
                    gg += fmaf(sm, vg.x, vg.y);
                    go += fmaf(sm, vo.x, vo.y);
                    float cc = csm[row * 257 + u];
                    float cm = fmaf(fsig(gf), cc, fsig(gi) * ftanh(gg));
                    csm[row * 257 + u] = cm;
                    float hv = fsig(go) * ftanh(cm);
                    __nv_bfloat16 hbv = __float2bfloat16(hv);
                    Wh_[row * HPAD + u] = hbv;
                    Wl_[row * HPAD + u] = __float2bfloat16(hv - __bfloat162float(hbv));
                }
            }
            __syncthreads();   // h(wbuf) complete before next step reads it
        }

        // Epilogue: partial[m][o] = h_last[m] @ W_lin[l]
        {
            const __nv_bfloat16* Fh = hb + (size_t)((len & 1) * 2 + 0) * 16 * HPAD;
            const __nv_bfloat16* Fl = hb + (size_t)((len & 1) * 2 + 1) * 16 * HPAD;
            for (int i = tid; i < MB * OUT_; i += 128) {
                int m = i / OUT_, o = i - m * OUT_;
                const float* wl = W_lin + (size_t)l * H_ * OUT_ + o;
                float s = 0.f;
#pragma unroll 8
                for (int u = 0; u < H_; u++) {
                    float hv = __bfloat162float(Fh[m * HPAD + u]) +
                               __bfloat162float(Fl[m * HPAD + u]);
                    s = fmaf(hv, __ldg(wl + u * OUT_), s);
                }
                g_partial[(job * MB + m) * OUT_ + o] = s;
            }
        }
        __syncthreads();   // protect smem before next job
    }
}

// ---------------------------------------------------------------------------
__global__ void reduce_kernel(const float* __restrict__ b_lin,
                              float* __restrict__ out) {
    int i = blockIdx.x * blockDim.x + threadIdx.x;
    if (i >= B_ * OUT_) return;
    int b = i / OUT_, o = i % OUT_;
    int bc = b / MB, m = b % MB;
    float s = 0.f;
#pragma unroll
    for (int l = 0; l < LVLS; l++) {
        s += b_lin[l * OUT_ + o];
        for (int t = 0; t < NT; t++) {
            int job = (l * NT + t) * BC + bc;
            s += g_partial[(job * MB + m) * OUT_ + o];
        }
    }
    out[i] = s;
}

// ---------------------------------------------------------------------------
extern "C" void kernel_launch(void* const* d_in, const int* in_sizes, int n_in,
                              void* d_out, int out_size) {
    const float* batch_feature = (const float*)d_in[0];
    const int*   trunk_idx     = (const int*)  d_in[1];
    const int*   trunk_len     = (const int*)  d_in[2];
    const float* W_enc         = (const float*)d_in[3];
    const float* b_enc         = (const float*)d_in[4];
    const float* W_ih          = (const float*)d_in[5];
    const float* W_hh          = (const float*)d_in[6];
    const float* b_ih          = (const float*)d_in[7];
    const float* b_hh          = (const float*)d_in[8];
    const float* W_lin         = (const float*)d_in[9];
    const float* b_lin         = (const float*)d_in[10];
    float* out = (float*)d_out;

    cudaFuncSetAttribute(lstm_kernel,
                         cudaFuncAttributeMaxDynamicSharedMemorySize, SM_SZ);

    prep_kernel<<<384, 256>>>(W_ih, W_enc, b_enc, b_ih, b_hh, W_hh);
    order_kernel<<<1, NJOBS>>>(trunk_len);
    lstm_kernel<<<296, 128, SM_SZ>>>(batch_feature, trunk_idx, trunk_len, W_lin);
    reduce_kernel<<<(B_ * OUT_ + 127) / 128, 128>>>(b_lin, out);
}

// round 17
// speedup vs baseline: 5.4411x; 1.5685x over previous
#include <cuda_runtime.h>
#include <cuda_fp16.h>
#include <cstdint>

#define B_    64
#define N_    128
#define LVLS  3
#define NT    32
#define TL    32
#define H_    256
#define OUT_  10
#define BC    2
#define MB    32
#define NJOBS (LVLS*NT*BC)   // 192

// SMEM layout (bytes). h: fp16 [buf2][32][HPAD]
#define HPAD  264
#define SM_H    0                         // 2*32*264*2 = 33792
#define SM_C    33792                     // float c[32][257] = 32896
#define SM_VU   66688                     // float2 vu[1024] = 8192
#define SM_SST  74880                     // float sst[32][32] = 4096
#define SM_IDX  78976                     // int idx[32] = 128
#define SM_MISC 79104                     // int misc[2]
#define SM_SZ   79232

// W fragment-linear (fp16): [l][nt 128][ks 16][lane 32] uint2{b0,b1}
__device__ uint2  g_Wf[(size_t)LVLS * 128 * 16 * 32];   // 1.5 MB
__device__ float2 g_vu[LVLS * 1024];
__device__ float  g_partial[NJOBS * MB * OUT_];
__device__ int    g_order[NJOBS];
__device__ int    g_ticket;

__device__ __forceinline__ void mma_f16(float* d, uint32_t a0, uint32_t a1,
                                        uint32_t a2, uint32_t a3,
                                        uint32_t b0, uint32_t b1) {
    asm volatile(
        "mma.sync.aligned.m16n8k16.row.col.f32.f16.f16.f32 "
        "{%0,%1,%2,%3}, {%4,%5,%6,%7}, {%8,%9}, {%0,%1,%2,%3};"
        : "+f"(d[0]), "+f"(d[1]), "+f"(d[2]), "+f"(d[3])
        : "r"(a0), "r"(a1), "r"(a2), "r"(a3), "r"(b0), "r"(b1));
}
__device__ __forceinline__ float fsig(float x)  { return __fdividef(1.0f, 1.0f + __expf(-x)); }
__device__ __forceinline__ float ftanh(float x) {
    float s = __fdividef(1.0f, 1.0f + __expf(-2.0f * x));
    return fmaf(2.0f, s, -1.0f);
}
__device__ __forceinline__ uint32_t pk_hf2(float a, float b) {
    __half2 h2 = __floats2half2_rn(a, b);
    return *reinterpret_cast<uint32_t*>(&h2);
}

// ---------------------------------------------------------------------------
// prep: one WARP per (l,row). Produces vu[gc] and fp16 mma B-fragment-linear
// W images (fragment geometry identical to the proven bf16 version).
// ---------------------------------------------------------------------------
__global__ void prep_kernel(const float* __restrict__ W_ih,
                            const float* __restrict__ W_enc,
                            const float* __restrict__ b_enc,
                            const float* __restrict__ b_ih,
                            const float* __restrict__ b_hh,
                            const float* __restrict__ W_hh) {
    __shared__ float we[H_], be[H_];
    int tid = threadIdx.x;
    we[tid] = W_enc[tid]; be[tid] = b_enc[tid];
    __syncthreads();

    int wg  = blockIdx.x * 8 + (tid >> 5);   // 0..3071 = (l,row)
    int lane = tid & 31;
    int l = wg >> 10, row = wg & 1023;
    int g = row >> 8, u = row & 255;
    int gc = 4 * u + g;
    int nt = gc >> 3, lgrp = gc & 7;
    const float* Wi = W_ih + (size_t)wg * H_;
    const float* Wh = W_hh + (size_t)wg * H_;

    float sv = 0.f, su = 0.f;
#pragma unroll
    for (int rep = 0; rep < 2; rep++) {
        int slot = lane + 32 * rep;          // 0..63
        int ks = slot >> 2, tg = slot & 3;
        int k0 = ks * 16 + tg * 2;
        float wa = Wi[k0], wb = Wi[k0 + 1], wc = Wi[k0 + 8], wd = Wi[k0 + 9];
        sv += wa * we[k0] + wb * we[k0 + 1] + wc * we[k0 + 8] + wd * we[k0 + 9];
        su += wa * be[k0] + wb * be[k0 + 1] + wc * be[k0 + 8] + wd * be[k0 + 9];
        uint2 frag;
        frag.x = pk_hf2(Wh[k0], Wh[k0 + 1]);       // b0 (k0,k0+1)
        frag.y = pk_hf2(Wh[k0 + 8], Wh[k0 + 9]);   // b1 (k0+8,k0+9)
        g_Wf[(((size_t)l * 128 + nt) * 16 + ks) * 32 + lgrp * 4 + tg] = frag;
    }
#pragma unroll
    for (int o = 16; o; o >>= 1) {
        sv += __shfl_xor_sync(0xffffffffu, sv, o);
        su += __shfl_xor_sync(0xffffffffu, su, o);
    }
    if (lane == 0)
        g_vu[l * 1024 + gc] = make_float2(sv, su + b_ih[wg] + b_hh[wg]);
}

// ---------------------------------------------------------------------------
// order: LPT rank + ticket reset. job = (l*NT+t)*2 + bch; length from t only.
// ---------------------------------------------------------------------------
__global__ void order_kernel(const int* __restrict__ trunk_len) {
    __shared__ int len_s[NJOBS];
    int i = threadIdx.x;                 // 0..191
    int l = i >> 6, t = (i >> 1) & 31;
    int L = trunk_len[l * NT + t];
    L = min(max(L, 1), TL);
    len_s[i] = L;
    __syncthreads();
    int Li = len_s[i];
    int rank = 0;
    for (int k = 0; k < NJOBS; k++) {
        int Lk = len_s[k];
        rank += (Lk > Li) || (Lk == Li && k < i);
    }
    g_order[rank] = i;
    if (i == 0) g_ticket = 0;
}

// ---------------------------------------------------------------------------
// LSTM via mma.sync, 1-pass fp16, M=32 jobs (both bc-halves of one trunk:
// shared idx/len/B). 256 threads (8 warps); warp w owns gate cols
// [w*128,(w+1)*128), two m16 row-blocks per B fragment. Persistent CTAs
// (grid 148) + LPT ticket; h double-buffered; 1 barrier/step.
// ---------------------------------------------------------------------------
__global__ void __launch_bounds__(256, 1)
lstm_kernel(const float* __restrict__ bf,
            const int*   __restrict__ trunk_idx,
            const int*   __restrict__ trunk_len,
            const float* __restrict__ W_lin) {
    extern __shared__ char smem[];
    __half* hb  = reinterpret_cast<__half*>(smem + SM_H);
    float*  csm = reinterpret_cast<float*>(smem + SM_C);
    float2* vu  = reinterpret_cast<float2*>(smem + SM_VU);
    float*  sst = reinterpret_cast<float*>(smem + SM_SST);
    int*    idx = reinterpret_cast<int*>(smem + SM_IDX);
    int*    misc = reinterpret_cast<int*>(smem + SM_MISC);

    const int tid = threadIdx.x, lane = tid & 31, warp = tid >> 5;
    const int g = lane >> 2, tg = lane & 3;

    for (;;) {
        if (tid == 0) {
            int tk = atomicAdd(&g_ticket, 1);
            misc[0] = (tk < NJOBS) ? g_order[tk] : -1;
        }
        __syncthreads();
        const int job = misc[0];
        if (job < 0) break;
        const int l = job >> 6, t = (job >> 1) & 31, bch = job & 1;

        if (tid < TL) idx[tid] = trunk_idx[(l * NT + t) * TL + tid];
        if (tid == 0) misc[1] = min(max(trunk_len[l * NT + t], 1), TL);
        __syncthreads();
        for (int i = tid; i < 1024; i += 256) vu[i] = g_vu[l * 1024 + i];
        for (int i = tid; i < 32 * MB; i += 256)
            sst[i] = bf[(bch * MB + (i & 31)) * N_ + idx[i >> 5]];
        for (int i = tid; i < 8448; i += 256)
            reinterpret_cast<uint32_t*>(hb)[i] = 0;      // zero both h bufs
        for (int i = tid; i < MB * 257; i += 256) csm[i] = 0.f;
        __syncthreads();
        const int len = misc[1];

        const uint2* gW = g_Wf + (size_t)l * 128 * 16 * 32;

        for (int step = 0; step < len; step++) {
            const int rbuf = step & 1, wbuf = rbuf ^ 1;
            const __half* Hh = hb + (size_t)rbuf * MB * HPAD;
            __half* Wh_ = hb + (size_t)wbuf * MB * HPAD;

#pragma unroll 1
            for (int ch = 0; ch < 2; ch++) {
                float D[8][2][4];
#pragma unroll
                for (int q = 0; q < 8; q++)
#pragma unroll
                    for (int m = 0; m < 2; m++)
#pragma unroll
                        for (int e = 0; e < 4; e++) D[q][m][e] = 0.f;

#pragma unroll 4
                for (int ks = 0; ks < 16; ks++) {
                    const int c0 = ks * 16 + tg * 2;
                    uint32_t a[2][4];
#pragma unroll
                    for (int m = 0; m < 2; m++) {
                        const int r0 = m * 16 + g;
                        a[m][0] = *reinterpret_cast<const uint32_t*>(Hh + r0 * HPAD + c0);
                        a[m][1] = *reinterpret_cast<const uint32_t*>(Hh + (r0 + 8) * HPAD + c0);
                        a[m][2] = *reinterpret_cast<const uint32_t*>(Hh + r0 * HPAD + c0 + 8);
                        a[m][3] = *reinterpret_cast<const uint32_t*>(Hh + (r0 + 8) * HPAD + c0 + 8);
                    }
#pragma unroll
                    for (int q = 0; q < 8; q++) {
                        const int nt = warp * 16 + ch * 8 + q;
                        const uint2 Bv = __ldg(gW + ((size_t)nt * 16 + ks) * 32 + lane);
                        mma_f16(D[q][0], a[0][0], a[0][1], a[0][2], a[0][3], Bv.x, Bv.y);
                        mma_f16(D[q][1], a[1][0], a[1][1], a[1][2], a[1][3], Bv.x, Bv.y);
                    }
                }

                // Activations (proven mapping; row offset per m-block)
#pragma unroll
                for (int q = 0; q < 8; q++) {
#pragma unroll
                    for (int m = 0; m < 2; m++) {
                        float* d = D[q][m];
                        float x0 = __shfl_xor_sync(0xffffffffu, d[0], 1);
                        float x1 = __shfl_xor_sync(0xffffffffu, d[1], 1);
                        float x2 = __shfl_xor_sync(0xffffffffu, d[2], 1);
                        float x3 = __shfl_xor_sync(0xffffffffu, d[3], 1);
                        const int odd = tg & 1;
                        const int u = warp * 32 + (ch * 8 + q) * 2 + (tg >> 1);
                        const int row = m * 16 + g + 8 * odd;
                        float gi = odd ? x2 : d[0];
                        float gf = odd ? x3 : d[1];
                        float gg = odd ? d[2] : x0;
                        float go = odd ? d[3] : x1;
                        const float sm = sst[step * MB + row];
                        float2 vi = vu[4 * u], vf = vu[4 * u + 1],
                               vg = vu[4 * u + 2], vo = vu[4 * u + 3];
                        gi += fmaf(sm, vi.x, vi.y);
                        gf += fmaf(sm, vf.x, vf.y);
                        gg += fmaf(sm, vg.x, vg.y);
                        go += fmaf(sm, vo.x, vo.y);
                        float cc = csm[row * 257 + u];
                        float cm = fmaf(fsig(gf), cc, fsig(gi) * ftanh(gg));
                        csm[row * 257 + u] = cm;
                        float hv = fsig(go) * ftanh(cm);
                        Wh_[row * HPAD + u] = __float2half(hv);
                    }
                }
            }
            __syncthreads();   // h(wbuf) complete before next step reads it
        }

        // Epilogue: partial[m][o] = h_last[m] @ W_lin[l]
        {
            const __half* Fh = hb + (size_t)(len & 1) * MB * HPAD;
            for (int i = tid; i < MB * OUT_; i += 256) {
                int m = i / OUT_, o = i - m * OUT_;
                const float* wl = W_lin + (size_t)l * H_ * OUT_ + o;
                float s = 0.f;
#pragma unroll 8
                for (int u = 0; u < H_; u++)
                    s = fmaf(__half2float(Fh[m * HPAD + u]), __ldg(wl + u * OUT_), s);
                g_partial[(job * MB + m) * OUT_ + o] = s;
            }
        }
        __syncthreads();   // protect smem before next job
    }
}

// ---------------------------------------------------------------------------
__global__ void reduce_kernel(const float* __restrict__ b_lin,
                              float* __restrict__ out) {
    int i = blockIdx.x * blockDim.x + threadIdx.x;
    if (i >= B_ * OUT_) return;
    int b = i / OUT_, o = i % OUT_;
    int bch = b / MB, m = b % MB;
    float s = 0.f;
#pragma unroll
    for (int l = 0; l < LVLS; l++) {
        s += b_lin[l * OUT_ + o];
        for (int t = 0; t < NT; t++) {
            int job = (l * NT + t) * BC + bch;
            s += g_partial[(job * MB + m) * OUT_ + o];
        }
    }
    out[i] = s;
}

// ---------------------------------------------------------------------------
extern "C" void kernel_launch(void* const* d_in, const int* in_sizes, int n_in,
                              void* d_out, int out_size) {
    const float* batch_feature = (const float*)d_in[0];
    const int*   trunk_idx     = (const int*)  d_in[1];
    const int*   trunk_len     = (const int*)  d_in[2];
    const float* W_enc         = (const float*)d_in[3];
    const float* b_enc         = (const float*)d_in[4];
    const float* W_ih          = (const float*)d_in[5];
    const float* W_hh          = (const float*)d_in[6];
    const float* b_ih          = (const float*)d_in[7];
    const float* b_hh          = (const float*)d_in[8];
    const float* W_lin         = (const float*)d_in[9];
    const float* b_lin         = (const float*)d_in[10];
    float* out = (float*)d_out;

    cudaFuncSetAttribute(lstm_kernel,
                         cudaFuncAttributeMaxDynamicSharedMemorySize, SM_SZ);

    prep_kernel<<<384, 256>>>(W_ih, W_enc, b_enc, b_ih, b_hh, W_hh);
    order_kernel<<<1, NJOBS>>>(trunk_len);
    lstm_kernel<<<148, 256, SM_SZ>>>(batch_feature, trunk_idx, trunk_len, W_lin);
    reduce_kernel<<<(B_ * OUT_ + 127) / 128, 128>>>(b_lin, out);
}